// round 10
// baseline (speedup 1.0000x reference)
#include <cuda_runtime.h>
#include <cstdint>

#define MD   128
#define NH   8
#define DV   16
#define NMAX 50000
#define EMAX 1600000
#define CAP  256
#define TMN  32
#define SB   512

typedef unsigned long long ull;

// ---------------- scratch (static device arrays; no cudaMalloc) -------------
__device__ float g_value[(size_t)NMAX * MD];   // [N,128] value projection
__device__ float g_vsrc[NMAX * NH];            // [N,8]
__device__ float g_vtgt[NMAX * NH];            // [N,8]
__device__ float g_mx[NMAX * NH];              // per-node per-head score max
__device__ float g_asum[NMAX * NH];            // per-node per-head weight sum
__device__ int   g_cnt[NMAX];                  // in-degree histogram
__device__ int   g_off[NMAX + 1];              // CSR offsets (exclusive scan)
__device__ int   g_cursor[NMAX];               // scatter cursors
__device__ int2  g_csr[EMAX];                  // (src, eid) per CSR slot
__device__ int   g_bsum[1024];                 // scan block sums
__device__ int   g_bpre[1024];                 // scan block prefixes

// ---------------- K0: reset histogram ---------------------------------------
__global__ void k_init(int N) {
    int i = blockIdx.x * blockDim.x + threadIdx.x;
    if (i < N) g_cnt[i] = 0;
}

// ---------------- K1: node projections, f32x2 packed FMA --------------------
__global__ void __launch_bounds__(256) k_node(
        const float* __restrict__ inp,
        const float* __restrict__ Wv,
        const float* __restrict__ ws,
        const float* __restrict__ wt,
        const float* __restrict__ Wself,
        const float* __restrict__ bias,
        float* __restrict__ out, int N) {
    __shared__ float A[TMN][MD];        // 16 KB, k-contiguous rows
    __shared__ float Wsh[2][128][20];   // per-kt staged 16-col chunk, padded

    const int tid = threadIdx.x;
    const int n0  = blockIdx.x * TMN;
    const int grp = tid >> 7;
    const int j   = tid & 127;

    for (int idx = tid; idx < TMN * MD; idx += 256) {
        int m = idx >> 7, k = idx & 127;
        int n = n0 + m;
        A[m][k] = (n < N) ? inp[(size_t)n * MD + k] : 0.f;
    }

    ull acc[TMN];
#pragma unroll
    for (int m = 0; m < TMN; m++) acc[m] = 0ull;

    for (int kt = 0; kt < MD; kt += 16) {
        __syncthreads();
        for (int i = tid; i < 1024; i += 256) {
            int g = i >> 9;
            int r = (i >> 2) & 127;
            int q = i & 3;
            const float* Wg = g ? Wself : Wv;
            float4 w4 = *(const float4*)&Wg[r * MD + kt + 4 * q];
            *(float4*)&Wsh[g][r][4 * q] = w4;
        }
        __syncthreads();

        ull wp[8];
#pragma unroll
        for (int q = 0; q < 8; q++)
            wp[q] = *(const ull*)&Wsh[grp][j][2 * q];

#pragma unroll
        for (int m = 0; m < TMN; m++) {
#pragma unroll
            for (int q4 = 0; q4 < 4; q4++) {
                float4 a4 = *(const float4*)&A[m][kt + 4 * q4];
                ull alo, ahi;
                asm("mov.b64 %0, {%1,%2};" : "=l"(alo) : "f"(a4.x), "f"(a4.y));
                asm("mov.b64 %0, {%1,%2};" : "=l"(ahi) : "f"(a4.z), "f"(a4.w));
                asm("fma.rn.f32x2 %0, %1, %2, %3;"
                    : "=l"(acc[m]) : "l"(alo), "l"(wp[2 * q4]), "l"(acc[m]));
                asm("fma.rn.f32x2 %0, %1, %2, %3;"
                    : "=l"(acc[m]) : "l"(ahi), "l"(wp[2 * q4 + 1]), "l"(acc[m]));
            }
        }
    }

    const int h = j >> 4, d = j & 15;
    float wsj = 0.f, wtj = 0.f, bj = 0.f;
    if (grp == 0) { wsj = ws[j]; wtj = wt[j]; }
    else          { bj = bias[j]; }

#pragma unroll
    for (int m = 0; m < TMN; m++) {
        int n = n0 + m;
        float lo, hi;
        asm("mov.b64 {%0,%1}, %2;" : "=f"(lo), "=f"(hi) : "l"(acc[m]));
        float v = lo + hi;
        if (grp == 0) {
            if (n < N) g_value[(size_t)n * MD + j] = v;
            float t1 = v * wsj;
            float t2 = v * wtj;
#pragma unroll
            for (int o = 8; o > 0; o >>= 1) {
                t1 += __shfl_xor_sync(0xffffffffu, t1, o);
                t2 += __shfl_xor_sync(0xffffffffu, t2, o);
            }
            if (d == 0 && n < N) {
                g_vsrc[n * NH + h] = t1;
                g_vtgt[n * NH + h] = t2;
            }
        } else {
            if (n < N) out[(size_t)n * MD + j] = v + bj;
        }
    }
}

// ---------------- K2: in-degree histogram (tgt row only) --------------------
__global__ void k_hist(const int* __restrict__ ei, int E) {
    int e = blockIdx.x * blockDim.x + threadIdx.x;
    if (e < E) atomicAdd(&g_cnt[ei[E + e]], 1);
}

// ---------------- K3a/b/c: multi-block exclusive scan -----------------------
__global__ void k_scan1(int N) {
    __shared__ int sh[SB];
    int tid = threadIdx.x;
    int i = blockIdx.x * SB + tid;
    int v = (i < N) ? g_cnt[i] : 0;
    sh[tid] = v;
    __syncthreads();
    for (int o = 1; o < SB; o <<= 1) {
        int t = (tid >= o) ? sh[tid - o] : 0;
        __syncthreads();
        sh[tid] += t;
        __syncthreads();
    }
    if (i < N) g_off[i] = sh[tid] - v;
    if (tid == SB - 1) g_bsum[blockIdx.x] = sh[SB - 1];
}

__global__ void k_scan2(int nb, int N) {
    __shared__ int sh[1024];
    int tid = threadIdx.x;
    int v = (tid < nb) ? g_bsum[tid] : 0;
    sh[tid] = v;
    __syncthreads();
    for (int o = 1; o < 1024; o <<= 1) {
        int t = (tid >= o) ? sh[tid - o] : 0;
        __syncthreads();
        sh[tid] += t;
        __syncthreads();
    }
    if (tid < nb) g_bpre[tid] = sh[tid] - v;
    if (tid == 1023) g_off[N] = sh[1023];
}

__global__ void k_scan3(int N) {
    int i = blockIdx.x * SB + threadIdx.x;
    if (i < N) {
        int o = g_off[i] + g_bpre[blockIdx.x];
        g_off[i] = o;
        g_cursor[i] = o;
    }
}

// ---------------- K4: scatter edges into CSR (packed int2) ------------------
__global__ void k_scatter(const int* __restrict__ ei, int E) {
    int e = blockIdx.x * blockDim.x + threadIdx.x;
    if (e < E) {
        int s = ei[e];
        int t = ei[E + e];
        int p = atomicAdd(&g_cursor[t], 1);
        g_csr[p] = make_int2(s, e);
    }
}

// ---------------- K5: per-target softmax stats + aggregation ----------------
// Stores per-node (mx, asum) for the edge-parallel attn kernel; aggregates
// with unnormalized weights and divides once at the end (exact factorization).
__global__ void k_aggregate(const float* __restrict__ dist,
                            float* __restrict__ out, int N) {
    int n   = blockIdx.x;
    int tid = threadIdx.x;
    int base = g_off[n];
    int deg  = g_off[n + 1] - base;
    if (deg == 0) return;

    __shared__ float s_vtgt[NH];
    __shared__ float s_mx[NH], s_asum[NH];
    __shared__ float s_part[128];
    __shared__ float s_exp[CAP * NH];
    __shared__ int   s_src[CAP], s_eid[CAP];
    __shared__ int   t_src[CAP], t_eid[CAP];
    __shared__ float s_dist[CAP];

    if (tid < NH) s_vtgt[tid] = g_vtgt[n * NH + tid];
    int h  = tid & 7;    // head in (edge,head)-strided loops
    int hc = tid >> 4;   // head of this output column

    if (deg <= CAP) {
        for (int i = tid; i < deg; i += 128) {
            int2 se = g_csr[base + i];
            s_src[i] = se.x;
            s_eid[i] = se.y;
        }
        __syncthreads();
        // deterministic rank-sort by original edge id
        for (int i = tid; i < deg; i += 128) {
            int key = s_eid[i];
            int r = 0;
            for (int q = 0; q < deg; q++) r += (s_eid[q] < key);
            t_eid[r] = key;
            t_src[r] = s_src[i];
        }
        __syncthreads();
        for (int i = tid; i < deg; i += 128) s_dist[i] = dist[t_eid[i]];
        __syncthreads();

        // pass1: scores + per-head max
        float mloc = -1e30f;
        for (int idx = tid; idx < deg * NH; idx += 128) {
            int e = idx >> 3;
            float s = g_vsrc[t_src[e] * NH + h] + s_vtgt[h];
            s = s > 0.f ? s : 0.2f * s;
            s_exp[idx] = s;
            mloc = fmaxf(mloc, s);
        }
        s_part[tid] = mloc;
        __syncthreads();
        if (tid < NH) {
            float v = -1e30f;
#pragma unroll
            for (int k = 0; k < 16; k++) v = fmaxf(v, s_part[tid + 8 * k]);
            s_mx[tid] = v;
            g_mx[n * NH + tid] = v;
        }
        __syncthreads();

        // pass2: w = exp(s - m)/dist, per-head sum (sorted order -> deterministic)
        float aloc = 0.f;
        for (int idx = tid; idx < deg * NH; idx += 128) {
            int e = idx >> 3;
            float w = __expf(s_exp[idx] - s_mx[h]) / s_dist[e];
            s_exp[idx] = w;
            aloc += w;
        }
        s_part[tid] = aloc;
        __syncthreads();
        if (tid < NH) {
            float v = 0.f;
#pragma unroll
            for (int k = 0; k < 16; k++) v += s_part[tid + 8 * k];
            s_asum[tid] = v;
            g_asum[n * NH + tid] = v;
        }
        __syncthreads();

        // pass3: weighted aggregation with unnormalized w; divide at end
        float acc = 0.f;
#pragma unroll 4
        for (int e = 0; e < deg; e++)
            acc += s_exp[e * NH + hc] * g_value[(size_t)t_src[e] * MD + tid];
        out[(size_t)n * MD + tid] += acc / s_asum[hc];
    } else {
        // ---- fallback (deg > CAP): recompute-based, chunked ----
        __syncthreads();
        float mloc = -1e30f;
        for (int idx = tid; idx < deg * NH; idx += 128) {
            int e = idx >> 3;
            float s = g_vsrc[g_csr[base + e].x * NH + h] + s_vtgt[h];
            s = s > 0.f ? s : 0.2f * s;
            mloc = fmaxf(mloc, s);
        }
        s_part[tid] = mloc;
        __syncthreads();
        if (tid < NH) {
            float v = -1e30f;
            for (int k = 0; k < 16; k++) v = fmaxf(v, s_part[tid + 8 * k]);
            s_mx[tid] = v;
            g_mx[n * NH + tid] = v;
        }
        __syncthreads();
        float aloc = 0.f;
        for (int idx = tid; idx < deg * NH; idx += 128) {
            int e = idx >> 3;
            int2 se = g_csr[base + e];
            float s = g_vsrc[se.x * NH + h] + s_vtgt[h];
            s = s > 0.f ? s : 0.2f * s;
            aloc += __expf(s - s_mx[h]) / dist[se.y];
        }
        s_part[tid] = aloc;
        __syncthreads();
        if (tid < NH) {
            float v = 0.f;
            for (int k = 0; k < 16; k++) v += s_part[tid + 8 * k];
            s_asum[tid] = v;
            g_asum[n * NH + tid] = v;
        }
        __syncthreads();
        float acc = 0.f;
        for (int c0 = 0; c0 < deg; c0 += CAP) {
            int clen = min(CAP, deg - c0);
            for (int i = tid; i < clen; i += 128) {
                int2 se = g_csr[base + c0 + i];
                t_src[i] = se.x;
                t_eid[i] = se.y;
            }
            __syncthreads();
            for (int i = tid; i < clen; i += 128) s_dist[i] = dist[t_eid[i]];
            __syncthreads();
            for (int idx = tid; idx < clen * NH; idx += 128) {
                int e = idx >> 3;
                float s = g_vsrc[t_src[e] * NH + h] + s_vtgt[h];
                s = s > 0.f ? s : 0.2f * s;
                s_exp[idx] = __expf(s - s_mx[h]) / s_dist[e];
            }
            __syncthreads();
            for (int e = 0; e < clen; e++)
                acc += s_exp[e * NH + hc] * g_value[(size_t)t_src[e] * MD + tid];
            __syncthreads();
        }
        out[(size_t)n * MD + tid] += acc / s_asum[hc];
    }
}

// ---------------- K6: edge-parallel attn (coalesced writes) -----------------
// attn[e,h] = exp(lrelu(vsrc[s,h]+vtgt[t,h]) - mx[t,h]) / dist[e] / asum[t,h]
__global__ void k_attn(const int* __restrict__ ei,
                       const float* __restrict__ dist,
                       float* __restrict__ attn_out, int E) {
    int e = blockIdx.x * blockDim.x + threadIdx.x;
    if (e >= E) return;
    int s = ei[e];
    int t = ei[E + e];
    const float4* vs4 = (const float4*)g_vsrc;
    const float4* vt4 = (const float4*)g_vtgt;
    const float4* mx4 = (const float4*)g_mx;
    const float4* as4 = (const float4*)g_asum;
    float4 a0 = vs4[s * 2], a1 = vs4[s * 2 + 1];
    float4 b0 = vt4[t * 2], b1 = vt4[t * 2 + 1];
    float4 m0 = mx4[t * 2], m1 = mx4[t * 2 + 1];
    float4 u0 = as4[t * 2], u1 = as4[t * 2 + 1];
    float invd = 1.f / dist[e];

    float va[8] = {a0.x, a0.y, a0.z, a0.w, a1.x, a1.y, a1.z, a1.w};
    float vb[8] = {b0.x, b0.y, b0.z, b0.w, b1.x, b1.y, b1.z, b1.w};
    float vm[8] = {m0.x, m0.y, m0.z, m0.w, m1.x, m1.y, m1.z, m1.w};
    float vu[8] = {u0.x, u0.y, u0.z, u0.w, u1.x, u1.y, u1.z, u1.w};
    float r[8];
#pragma unroll
    for (int h = 0; h < 8; h++) {
        float sc = va[h] + vb[h];
        sc = sc > 0.f ? sc : 0.2f * sc;
        r[h] = __expf(sc - vm[h]) * invd / vu[h];
    }
    float4* o4 = (float4*)(attn_out + (size_t)e * NH);
    o4[0] = make_float4(r[0], r[1], r[2], r[3]);
    o4[1] = make_float4(r[4], r[5], r[6], r[7]);
}

// ---------------- launch -----------------------------------------------------
extern "C" void kernel_launch(void* const* d_in, const int* in_sizes, int n_in,
                              void* d_out, int out_size) {
    const float* inp   = (const float*)d_in[0];
    const int*   ei    = (const int*)d_in[1];
    const float* dist  = (const float*)d_in[2];
    // d_in[3] = deparc_edge (unused by the reference math)
    const float* Wv    = (const float*)d_in[4];
    const float* ws    = (const float*)d_in[5];
    const float* wt    = (const float*)d_in[6];
    const float* Wself = (const float*)d_in[7];
    const float* bias  = (const float*)d_in[8];

    int N = in_sizes[0] / MD;
    int E = in_sizes[2];
    int nb = (N + SB - 1) / SB;

    float* out  = (float*)d_out;
    float* attn = nullptr;
    if ((long long)out_size >= (long long)N * MD + (long long)E * NH)
        attn = out + (size_t)N * MD;

    k_init<<<(N + 255) / 256, 256>>>(N);
    k_node<<<(N + TMN - 1) / TMN, 256>>>(inp, Wv, ws, wt, Wself, bias, out, N);
    k_hist<<<(E + 255) / 256, 256>>>(ei, E);
    k_scan1<<<nb, SB>>>(N);
    k_scan2<<<1, 1024>>>(nb, N);
    k_scan3<<<nb, SB>>>(N);
    k_scatter<<<(E + 255) / 256, 256>>>(ei, E);
    k_aggregate<<<N, 128>>>(dist, out, N);
    if (attn) k_attn<<<(E + 255) / 256, 256>>>(ei, dist, attn, E);
}

// round 12
// speedup vs baseline: 1.0775x; 1.0775x over previous
#include <cuda_runtime.h>
#include <cstdint>

#define MD   128
#define NH   8
#define DV   16
#define NMAX 50000
#define EMAX 1600000
#define TMN  32
#define SB   512
#define SCAP 96          // per-warp edge capacity in k_aggregate
#define WPB  8           // warps (nodes) per aggregate block

typedef unsigned long long ull;

// ---------------- scratch (static device arrays; no cudaMalloc) -------------
__device__ float g_value[(size_t)NMAX * MD];   // [N,128] value projection
__device__ float g_vsrc[NMAX * NH];            // [N,8]
__device__ float g_vtgt[NMAX * NH];            // [N,8]
__device__ float g_mx[NMAX * NH];              // per-node per-head score max
__device__ float g_asum[NMAX * NH];            // per-node per-head weight sum
__device__ int   g_cnt[NMAX];                  // in-degree histogram
__device__ int   g_off[NMAX + 1];              // CSR offsets (exclusive scan)
__device__ int   g_cursor[NMAX];               // scatter cursors
__device__ int2  g_csr[EMAX];                  // (src, eid) per CSR slot
__device__ int   g_bsum[1024];                 // scan block sums
__device__ int   g_bpre[1024];                 // scan block prefixes

// ---------------- K0: reset histogram ---------------------------------------
__global__ void k_init(int N) {
    int i = blockIdx.x * blockDim.x + threadIdx.x;
    if (i < N) g_cnt[i] = 0;
}

// ---------------- K1: node projections, f32x2 packed FMA --------------------
__global__ void __launch_bounds__(256) k_node(
        const float* __restrict__ inp,
        const float* __restrict__ Wv,
        const float* __restrict__ ws,
        const float* __restrict__ wt,
        const float* __restrict__ Wself,
        const float* __restrict__ bias,
        float* __restrict__ out, int N) {
    __shared__ float A[TMN][MD];        // 16 KB, k-contiguous rows
    __shared__ float Wsh[2][128][20];   // per-kt staged 16-col chunk, padded

    const int tid = threadIdx.x;
    const int n0  = blockIdx.x * TMN;
    const int grp = tid >> 7;
    const int j   = tid & 127;

    for (int idx = tid; idx < TMN * MD; idx += 256) {
        int m = idx >> 7, k = idx & 127;
        int n = n0 + m;
        A[m][k] = (n < N) ? inp[(size_t)n * MD + k] : 0.f;
    }

    ull acc[TMN];
#pragma unroll
    for (int m = 0; m < TMN; m++) acc[m] = 0ull;

    for (int kt = 0; kt < MD; kt += 16) {
        __syncthreads();
        for (int i = tid; i < 1024; i += 256) {
            int g = i >> 9;
            int r = (i >> 2) & 127;
            int q = i & 3;
            const float* Wg = g ? Wself : Wv;
            float4 w4 = *(const float4*)&Wg[r * MD + kt + 4 * q];
            *(float4*)&Wsh[g][r][4 * q] = w4;
        }
        __syncthreads();

        ull wp[8];
#pragma unroll
        for (int q = 0; q < 8; q++)
            wp[q] = *(const ull*)&Wsh[grp][j][2 * q];

#pragma unroll
        for (int m = 0; m < TMN; m++) {
#pragma unroll
            for (int q4 = 0; q4 < 4; q4++) {
                float4 a4 = *(const float4*)&A[m][kt + 4 * q4];
                ull alo, ahi;
                asm("mov.b64 %0, {%1,%2};" : "=l"(alo) : "f"(a4.x), "f"(a4.y));
                asm("mov.b64 %0, {%1,%2};" : "=l"(ahi) : "f"(a4.z), "f"(a4.w));
                asm("fma.rn.f32x2 %0, %1, %2, %3;"
                    : "=l"(acc[m]) : "l"(alo), "l"(wp[2 * q4]), "l"(acc[m]));
                asm("fma.rn.f32x2 %0, %1, %2, %3;"
                    : "=l"(acc[m]) : "l"(ahi), "l"(wp[2 * q4 + 1]), "l"(acc[m]));
            }
        }
    }

    const int h = j >> 4, d = j & 15;
    float wsj = 0.f, wtj = 0.f, bj = 0.f;
    if (grp == 0) { wsj = ws[j]; wtj = wt[j]; }
    else          { bj = bias[j]; }

#pragma unroll
    for (int m = 0; m < TMN; m++) {
        int n = n0 + m;
        float lo, hi;
        asm("mov.b64 {%0,%1}, %2;" : "=f"(lo), "=f"(hi) : "l"(acc[m]));
        float v = lo + hi;
        if (grp == 0) {
            if (n < N) g_value[(size_t)n * MD + j] = v;
            float t1 = v * wsj;
            float t2 = v * wtj;
#pragma unroll
            for (int o = 8; o > 0; o >>= 1) {
                t1 += __shfl_xor_sync(0xffffffffu, t1, o);
                t2 += __shfl_xor_sync(0xffffffffu, t2, o);
            }
            if (d == 0 && n < N) {
                g_vsrc[n * NH + h] = t1;
                g_vtgt[n * NH + h] = t2;
            }
        } else {
            if (n < N) out[(size_t)n * MD + j] = v + bj;
        }
    }
}

// ---------------- K2: in-degree histogram (tgt row only) --------------------
__global__ void k_hist(const int* __restrict__ ei, int E) {
    int e = blockIdx.x * blockDim.x + threadIdx.x;
    if (e < E) atomicAdd(&g_cnt[ei[E + e]], 1);
}

// ---------------- K3a/b/c: multi-block exclusive scan -----------------------
__global__ void k_scan1(int N) {
    __shared__ int sh[SB];
    int tid = threadIdx.x;
    int i = blockIdx.x * SB + tid;
    int v = (i < N) ? g_cnt[i] : 0;
    sh[tid] = v;
    __syncthreads();
    for (int o = 1; o < SB; o <<= 1) {
        int t = (tid >= o) ? sh[tid - o] : 0;
        __syncthreads();
        sh[tid] += t;
        __syncthreads();
    }
    if (i < N) g_off[i] = sh[tid] - v;
    if (tid == SB - 1) g_bsum[blockIdx.x] = sh[SB - 1];
}

__global__ void k_scan2(int nb, int N) {
    __shared__ int sh[1024];
    int tid = threadIdx.x;
    int v = (tid < nb) ? g_bsum[tid] : 0;
    sh[tid] = v;
    __syncthreads();
    for (int o = 1; o < 1024; o <<= 1) {
        int t = (tid >= o) ? sh[tid - o] : 0;
        __syncthreads();
        sh[tid] += t;
        __syncthreads();
    }
    if (tid < nb) g_bpre[tid] = sh[tid] - v;
    if (tid == 1023) g_off[N] = sh[1023];
}

__global__ void k_scan3(int N) {
    int i = blockIdx.x * SB + threadIdx.x;
    if (i < N) {
        int o = g_off[i] + g_bpre[blockIdx.x];
        g_off[i] = o;
        g_cursor[i] = o;
    }
}

// ---------------- K4: scatter edges into CSR (packed int2) ------------------
__global__ void k_scatter(const int* __restrict__ ei, int E) {
    int e = blockIdx.x * blockDim.x + threadIdx.x;
    if (e < E) {
        int s = ei[e];
        int t = ei[E + e];
        int p = atomicAdd(&g_cursor[t], 1);
        g_csr[p] = make_int2(s, e);
    }
}

// ---------------- K5: warp-per-node softmax stats + aggregation -------------
// One warp handles one target node; no block-wide barriers. Stores per-node
// (mx, asum) for the edge-parallel attn kernel; aggregates with unnormalized
// weights and divides once at the end (exact factorization of the reference).
__global__ void __launch_bounds__(32 * WPB) k_aggregate(
        const float* __restrict__ dist,
        float* __restrict__ out, int N) {
    __shared__ int2  s_se[WPB][SCAP];
    __shared__ float s_w[WPB][SCAP * NH];
    __shared__ float s_dist[WPB][SCAP];
    __shared__ float s_red[WPB][2 * NH];   // [0..7]=mx, [8..15]=asum

    const int w    = threadIdx.x >> 5;
    const int lane = threadIdx.x & 31;
    const int n    = blockIdx.x * WPB + w;
    if (n >= N) return;

    int base = g_off[n];
    int deg  = g_off[n + 1] - base;
    if (deg == 0) return;

    // target biases in registers (same in all lanes)
    float4 vt0 = *(const float4*)&g_vtgt[n * NH];
    float4 vt1 = *(const float4*)&g_vtgt[n * NH + 4];
    float vt[8] = {vt0.x, vt0.y, vt0.z, vt0.w, vt1.x, vt1.y, vt1.z, vt1.w};

    float m[8], su[8];
#pragma unroll
    for (int h = 0; h < 8; h++) { m[h] = -1e30f; su[h] = 0.f; }

    const int hme = lane >> 2;                 // head of my 4 output columns

    if (deg <= SCAP) {
        // load CSR slots (unsorted)
        for (int i = lane; i < deg; i += 32)
            s_se[w][i] = g_csr[base + i];
        __syncwarp();
        // deterministic rank-sort by original edge id (<=3 owned per lane)
        int2 mye[3]; int myr[3]; int myc = 0;
#pragma unroll
        for (int k = 0; k < 3; k++) {
            int i = lane + 32 * k;
            if (i < deg) {
                int2 se = s_se[w][i];
                int r = 0;
                for (int q = 0; q < deg; q++) r += (s_se[w][q].y < se.y);
                mye[myc] = se; myr[myc] = r; myc++;
            }
        }
        __syncwarp();
#pragma unroll
        for (int k = 0; k < 3; k++)
            if (k < myc) s_se[w][myr[k]] = mye[k];
        __syncwarp();
        // dist per sorted slot
        for (int i = lane; i < deg; i += 32)
            s_dist[w][i] = dist[s_se[w][i].y];
        __syncwarp();

        // pass1: scores -> shared, per-head running max (lane-strided, sorted order)
        for (int i = lane; i < deg; i += 32) {
            int s = s_se[w][i].x;
            float4 a0 = *(const float4*)&g_vsrc[s * NH];
            float4 a1 = *(const float4*)&g_vsrc[s * NH + 4];
            float va[8] = {a0.x, a0.y, a0.z, a0.w, a1.x, a1.y, a1.z, a1.w};
#pragma unroll
            for (int h = 0; h < 8; h++) {
                float sc = va[h] + vt[h];
                sc = sc > 0.f ? sc : 0.2f * sc;
                s_w[w][i * NH + h] = sc;
                m[h] = fmaxf(m[h], sc);
            }
        }
#pragma unroll
        for (int o = 16; o > 0; o >>= 1)
#pragma unroll
            for (int h = 0; h < 8; h++)
                m[h] = fmaxf(m[h], __shfl_xor_sync(0xffffffffu, m[h], o));
        __syncwarp();

        // pass2: w = exp(s-m)/dist in shared, per-head sum
        for (int i = lane; i < deg; i += 32) {
            float invd = 1.f / s_dist[w][i];
#pragma unroll
            for (int h = 0; h < 8; h++) {
                float wv = __expf(s_w[w][i * NH + h] - m[h]) * invd;
                s_w[w][i * NH + h] = wv;
                su[h] += wv;
            }
        }
#pragma unroll
        for (int o = 16; o > 0; o >>= 1)
#pragma unroll
            for (int h = 0; h < 8; h++)
                su[h] += __shfl_xor_sync(0xffffffffu, su[h], o);

        if (lane == 0) {
#pragma unroll
            for (int h = 0; h < 8; h++) {
                s_red[w][h] = m[h];
                s_red[w][NH + h] = su[h];
                g_mx[n * NH + h] = m[h];
                g_asum[n * NH + h] = su[h];
            }
        }
        __syncwarp();

        // aggregation: lane covers cols 4*lane..4*lane+3 (coalesced 512B rows)
        float4 acc = make_float4(0.f, 0.f, 0.f, 0.f);
#pragma unroll 2
        for (int e = 0; e < deg; e++) {
            float wv = s_w[w][e * NH + hme];
            int s = s_se[w][e].x;
            float4 v = *(const float4*)&g_value[(size_t)s * MD + 4 * lane];
            acc.x += wv * v.x; acc.y += wv * v.y;
            acc.z += wv * v.z; acc.w += wv * v.w;
        }
        float inv = 1.f / s_red[w][NH + hme];
        float4* o4 = (float4*)&out[(size_t)n * MD + 4 * lane];
        float4 cur = *o4;
        cur.x += acc.x * inv; cur.y += acc.y * inv;
        cur.z += acc.z * inv; cur.w += acc.w * inv;
        *o4 = cur;
    } else {
        // ---- streaming fallback (deg > SCAP): recompute-based, chunked ----
        // pass1: max
        for (int i = lane; i < deg; i += 32) {
            int s = g_csr[base + i].x;
            float4 a0 = *(const float4*)&g_vsrc[s * NH];
            float4 a1 = *(const float4*)&g_vsrc[s * NH + 4];
            float va[8] = {a0.x, a0.y, a0.z, a0.w, a1.x, a1.y, a1.z, a1.w};
#pragma unroll
            for (int h = 0; h < 8; h++) {
                float sc = va[h] + vt[h];
                sc = sc > 0.f ? sc : 0.2f * sc;
                m[h] = fmaxf(m[h], sc);
            }
        }
#pragma unroll
        for (int o = 16; o > 0; o >>= 1)
#pragma unroll
            for (int h = 0; h < 8; h++)
                m[h] = fmaxf(m[h], __shfl_xor_sync(0xffffffffu, m[h], o));
        // pass2: sum
        for (int i = lane; i < deg; i += 32) {
            int2 se = g_csr[base + i];
            float4 a0 = *(const float4*)&g_vsrc[se.x * NH];
            float4 a1 = *(const float4*)&g_vsrc[se.x * NH + 4];
            float va[8] = {a0.x, a0.y, a0.z, a0.w, a1.x, a1.y, a1.z, a1.w};
            float invd = 1.f / dist[se.y];
#pragma unroll
            for (int h = 0; h < 8; h++) {
                float sc = va[h] + vt[h];
                sc = sc > 0.f ? sc : 0.2f * sc;
                su[h] += __expf(sc - m[h]) * invd;
            }
        }
#pragma unroll
        for (int o = 16; o > 0; o >>= 1)
#pragma unroll
            for (int h = 0; h < 8; h++)
                su[h] += __shfl_xor_sync(0xffffffffu, su[h], o);
        if (lane == 0) {
#pragma unroll
            for (int h = 0; h < 8; h++) {
                s_red[w][h] = m[h];
                s_red[w][NH + h] = su[h];
                g_mx[n * NH + h] = m[h];
                g_asum[n * NH + h] = su[h];
            }
        }
        __syncwarp();
        // pass3: chunked aggregation (32 edges per chunk)
        float4 acc = make_float4(0.f, 0.f, 0.f, 0.f);
        for (int c0 = 0; c0 < deg; c0 += 32) {
            int clen = min(32, deg - c0);
            if (lane < clen) {
                int2 se = g_csr[base + c0 + lane];
                s_se[w][lane] = se;
                float4 a0 = *(const float4*)&g_vsrc[se.x * NH];
                float4 a1 = *(const float4*)&g_vsrc[se.x * NH + 4];
                float va[8] = {a0.x, a0.y, a0.z, a0.w, a1.x, a1.y, a1.z, a1.w};
                float invd = 1.f / dist[se.y];
#pragma unroll
                for (int h = 0; h < 8; h++) {
                    float sc = va[h] + vt[h];
                    sc = sc > 0.f ? sc : 0.2f * sc;
                    s_w[w][lane * NH + h] = __expf(sc - m[h]) * invd;
                }
            }
            __syncwarp();
            for (int e = 0; e < clen; e++) {
                float wv = s_w[w][e * NH + hme];
                int s = s_se[w][e].x;
                float4 v = *(const float4*)&g_value[(size_t)s * MD + 4 * lane];
                acc.x += wv * v.x; acc.y += wv * v.y;
                acc.z += wv * v.z; acc.w += wv * v.w;
            }
            __syncwarp();
        }
        float inv = 1.f / s_red[w][NH + hme];
        float4* o4 = (float4*)&out[(size_t)n * MD + 4 * lane];
        float4 cur = *o4;
        cur.x += acc.x * inv; cur.y += acc.y * inv;
        cur.z += acc.z * inv; cur.w += acc.w * inv;
        *o4 = cur;
    }
}

// ---------------- K6: edge-parallel attn (coalesced writes) -----------------
__global__ void k_attn(const int* __restrict__ ei,
                       const float* __restrict__ dist,
                       float* __restrict__ attn_out, int E) {
    int e = blockIdx.x * blockDim.x + threadIdx.x;
    if (e >= E) return;
    int s = ei[e];
    int t = ei[E + e];
    const float4* vs4 = (const float4*)g_vsrc;
    const float4* vt4 = (const float4*)g_vtgt;
    const float4* mx4 = (const float4*)g_mx;
    const float4* as4 = (const float4*)g_asum;
    float4 a0 = vs4[s * 2], a1 = vs4[s * 2 + 1];
    float4 b0 = vt4[t * 2], b1 = vt4[t * 2 + 1];
    float4 m0 = mx4[t * 2], m1 = mx4[t * 2 + 1];
    float4 u0 = as4[t * 2], u1 = as4[t * 2 + 1];
    float invd = 1.f / dist[e];

    float va[8] = {a0.x, a0.y, a0.z, a0.w, a1.x, a1.y, a1.z, a1.w};
    float vb[8] = {b0.x, b0.y, b0.z, b0.w, b1.x, b1.y, b1.z, b1.w};
    float vm[8] = {m0.x, m0.y, m0.z, m0.w, m1.x, m1.y, m1.z, m1.w};
    float vu[8] = {u0.x, u0.y, u0.z, u0.w, u1.x, u1.y, u1.z, u1.w};
    float r[8];
#pragma unroll
    for (int h = 0; h < 8; h++) {
        float sc = va[h] + vb[h];
        sc = sc > 0.f ? sc : 0.2f * sc;
        r[h] = __expf(sc - vm[h]) * invd / vu[h];
    }
    float4* o4 = (float4*)(attn_out + (size_t)e * NH);
    o4[0] = make_float4(r[0], r[1], r[2], r[3]);
    o4[1] = make_float4(r[4], r[5], r[6], r[7]);
}

// ---------------- launch -----------------------------------------------------
extern "C" void kernel_launch(void* const* d_in, const int* in_sizes, int n_in,
                              void* d_out, int out_size) {
    const float* inp   = (const float*)d_in[0];
    const int*   ei    = (const int*)d_in[1];
    const float* dist  = (const float*)d_in[2];
    // d_in[3] = deparc_edge (unused by the reference math)
    const float* Wv    = (const float*)d_in[4];
    const float* ws    = (const float*)d_in[5];
    const float* wt    = (const float*)d_in[6];
    const float* Wself = (const float*)d_in[7];
    const float* bias  = (const float*)d_in[8];

    int N = in_sizes[0] / MD;
    int E = in_sizes[2];
    int nb = (N + SB - 1) / SB;

    float* out  = (float*)d_out;
    float* attn = nullptr;
    if ((long long)out_size >= (long long)N * MD + (long long)E * NH)
        attn = out + (size_t)N * MD;

    k_init<<<(N + 255) / 256, 256>>>(N);
    k_node<<<(N + TMN - 1) / TMN, 256>>>(inp, Wv, ws, wt, Wself, bias, out, N);
    k_hist<<<(E + 255) / 256, 256>>>(ei, E);
    k_scan1<<<nb, SB>>>(N);
    k_scan2<<<1, 1024>>>(nb, N);
    k_scan3<<<nb, SB>>>(N);
    k_scatter<<<(E + 255) / 256, 256>>>(ei, E);
    k_aggregate<<<(N + WPB - 1) / WPB, 32 * WPB>>>(dist, out, N);
    if (attn) k_attn<<<(E + 255) / 256, 256>>>(ei, dist, attn, E);
}

// round 13
// speedup vs baseline: 1.2067x; 1.1200x over previous
#include <cuda_runtime.h>
#include <cstdint>

#define MD   128
#define NH   8
#define NMAX 50000
#define EMAX 1600000
#define TMN  32
#define SCAP 128         // ELL width == per-warp edge capacity
#define WPB  8           // warps (nodes) per aggregate block
#define MAXOVF 1024

typedef unsigned long long ull;

// ---------------- scratch (static device arrays; no cudaMalloc) -------------
__device__ float g_value[(size_t)NMAX * MD];     // [N,128] value projection
__device__ float g_vsrc[NMAX * NH];              // [N,8]
__device__ float g_vtgt[NMAX * NH];              // [N,8]
__device__ int   g_cnt[NMAX];                    // in-degree (ELL cursor)
__device__ int2  g_ell[(size_t)NMAX * SCAP];     // (src, eid) per node slot
__device__ int   g_ovf_n;                        // overflow node count
__device__ int   g_ovf[MAXOVF];                  // overflow node ids

// ---------------- K0: reset counters ----------------------------------------
__global__ void k_init(int N) {
    int i = blockIdx.x * blockDim.x + threadIdx.x;
    if (i < N) g_cnt[i] = 0;
    if (i == 0) g_ovf_n = 0;
}

// ---------------- K1: node projections, f32x2 packed FMA --------------------
// 256 threads: group 0 (tid 0-127) -> W_value col j (+vsrc/vtgt reduce),
//              group 1 (tid 128-255) -> W_self col j (+bias -> out).
__global__ void __launch_bounds__(256) k_node(
        const float* __restrict__ inp,
        const float* __restrict__ Wv,
        const float* __restrict__ ws,
        const float* __restrict__ wt,
        const float* __restrict__ Wself,
        const float* __restrict__ bias,
        float* __restrict__ out, int N) {
    __shared__ float A[TMN][MD];        // 16 KB, k-contiguous rows
    __shared__ float Wsh[2][128][20];   // per-kt staged 16-col chunk, padded

    const int tid = threadIdx.x;
    const int n0  = blockIdx.x * TMN;
    const int grp = tid >> 7;
    const int j   = tid & 127;

    for (int idx = tid; idx < TMN * MD; idx += 256) {
        int m = idx >> 7, k = idx & 127;
        int n = n0 + m;
        A[m][k] = (n < N) ? inp[(size_t)n * MD + k] : 0.f;
    }

    ull acc[TMN];
#pragma unroll
    for (int m = 0; m < TMN; m++) acc[m] = 0ull;

    for (int kt = 0; kt < MD; kt += 16) {
        __syncthreads();
        // stage W[:, kt:kt+16] for both matrices, coalesced LDG.128
        for (int i = tid; i < 1024; i += 256) {
            int g = i >> 9;
            int r = (i >> 2) & 127;
            int q = i & 3;
            const float* Wg = g ? Wself : Wv;
            float4 w4 = *(const float4*)&Wg[r * MD + kt + 4 * q];
            *(float4*)&Wsh[g][r][4 * q] = w4;
        }
        __syncthreads();

        ull wp[8];
#pragma unroll
        for (int q = 0; q < 8; q++)
            wp[q] = *(const ull*)&Wsh[grp][j][2 * q];

#pragma unroll
        for (int m = 0; m < TMN; m++) {
#pragma unroll
            for (int q = 0; q < 8; q++) {
                ull ap = *(const ull*)&A[m][kt + 2 * q];   // LDS.64, pre-packed pair
                asm("fma.rn.f32x2 %0, %1, %2, %3;"
                    : "=l"(acc[m]) : "l"(ap), "l"(wp[q]), "l"(acc[m]));
            }
        }
    }

    const int h = j >> 4, d = j & 15;
    float wsj = 0.f, wtj = 0.f, bj = 0.f;
    if (grp == 0) { wsj = ws[j]; wtj = wt[j]; }
    else          { bj = bias[j]; }

#pragma unroll
    for (int m = 0; m < TMN; m++) {
        int n = n0 + m;
        float lo, hi;
        asm("mov.b64 {%0,%1}, %2;" : "=f"(lo), "=f"(hi) : "l"(acc[m]));
        float v = lo + hi;
        if (grp == 0) {
            if (n < N) g_value[(size_t)n * MD + j] = v;
            float t1 = v * wsj;
            float t2 = v * wtj;
#pragma unroll
            for (int o = 8; o > 0; o >>= 1) {
                t1 += __shfl_xor_sync(0xffffffffu, t1, o);
                t2 += __shfl_xor_sync(0xffffffffu, t2, o);
            }
            if (d == 0 && n < N) {
                g_vsrc[n * NH + h] = t1;
                g_vtgt[n * NH + h] = t2;
            }
        } else {
            if (n < N) out[(size_t)n * MD + j] = v + bj;
        }
    }
}

// ---------------- K2: build ELL adjacency directly --------------------------
__global__ void k_build(const int* __restrict__ ei, int E) {
    int e = blockIdx.x * blockDim.x + threadIdx.x;
    if (e < E) {
        int s = ei[e];
        int t = ei[E + e];
        int p = atomicAdd(&g_cnt[t], 1);
        if (p < SCAP) {
            g_ell[(size_t)t * SCAP + p] = make_int2(s, e);
        } else {
            int q = atomicAdd(&g_ovf_n, 1);
            if (q < MAXOVF) g_ovf[q] = t;   // duplicates OK; fixup is idempotent
        }
    }
}

// ---------------- K3: warp-per-node softmax + aggregation + attn ------------
// One warp per target node, no block-wide barriers. Final
// attn = (exp(lrelu(s)-mx)/dist) / asum  — the reference's global max and
// (denom+eps) divide out exactly. Aggregation divides by asum once at the end.
__global__ void __launch_bounds__(32 * WPB) k_aggregate(
        const float* __restrict__ dist,
        float* __restrict__ out,
        float* __restrict__ attn_out, int N) {
    __shared__ int2  s_se[WPB][SCAP];
    __shared__ float s_w[WPB][SCAP * NH];
    __shared__ float s_dist[WPB][SCAP];
    __shared__ float s_red[WPB][NH];       // asum per head

    const int w    = threadIdx.x >> 5;
    const int lane = threadIdx.x & 31;
    const int n    = blockIdx.x * WPB + w;
    if (n >= N) return;

    int deg = g_cnt[n];
    if (deg == 0 || deg > SCAP) return;    // overflow handled by k_fixup

    float4 vt0 = *(const float4*)&g_vtgt[n * NH];
    float4 vt1 = *(const float4*)&g_vtgt[n * NH + 4];
    float vt[8] = {vt0.x, vt0.y, vt0.z, vt0.w, vt1.x, vt1.y, vt1.z, vt1.w};

    float m[8], su[8];
#pragma unroll
    for (int h = 0; h < 8; h++) { m[h] = -1e30f; su[h] = 0.f; }

    const int hme = lane >> 2;             // head of my 4 output columns
    const size_t ebase = (size_t)n * SCAP;

    // load ELL slots (unsorted append order)
    for (int i = lane; i < deg; i += 32)
        s_se[w][i] = g_ell[ebase + i];
    __syncwarp();
    // deterministic rank-sort by original edge id (<=4 owned per lane)
    int2 mye[4]; int myr[4]; int myc = 0;
#pragma unroll
    for (int k = 0; k < 4; k++) {
        int i = lane + 32 * k;
        if (i < deg) {
            int2 se = s_se[w][i];
            int r = 0;
            for (int q = 0; q < deg; q++) r += (s_se[w][q].y < se.y);
            mye[myc] = se; myr[myc] = r; myc++;
        }
    }
    __syncwarp();
#pragma unroll
    for (int k = 0; k < 4; k++)
        if (k < myc) s_se[w][myr[k]] = mye[k];
    __syncwarp();
    for (int i = lane; i < deg; i += 32)
        s_dist[w][i] = dist[s_se[w][i].y];
    __syncwarp();

    // pass1: scores -> shared, per-head running max
    for (int i = lane; i < deg; i += 32) {
        int s = s_se[w][i].x;
        float4 a0 = *(const float4*)&g_vsrc[s * NH];
        float4 a1 = *(const float4*)&g_vsrc[s * NH + 4];
        float va[8] = {a0.x, a0.y, a0.z, a0.w, a1.x, a1.y, a1.z, a1.w};
#pragma unroll
        for (int h = 0; h < 8; h++) {
            float sc = va[h] + vt[h];
            sc = sc > 0.f ? sc : 0.2f * sc;
            s_w[w][i * NH + h] = sc;
            m[h] = fmaxf(m[h], sc);
        }
    }
#pragma unroll
    for (int o = 16; o > 0; o >>= 1)
#pragma unroll
        for (int h = 0; h < 8; h++)
            m[h] = fmaxf(m[h], __shfl_xor_sync(0xffffffffu, m[h], o));
    __syncwarp();

    // pass2: w = exp(s-m)/dist in shared, per-head sum
    for (int i = lane; i < deg; i += 32) {
        float invd = 1.f / s_dist[w][i];
#pragma unroll
        for (int h = 0; h < 8; h++) {
            float wv = __expf(s_w[w][i * NH + h] - m[h]) * invd;
            s_w[w][i * NH + h] = wv;
            su[h] += wv;
        }
    }
#pragma unroll
    for (int o = 16; o > 0; o >>= 1)
#pragma unroll
        for (int h = 0; h < 8; h++)
            su[h] += __shfl_xor_sync(0xffffffffu, su[h], o);

    if (lane == 0) {
#pragma unroll
        for (int h = 0; h < 8; h++) s_red[w][h] = su[h];
    }
    __syncwarp();

    // pass3: write attn at original edge positions (scattered 32B, fire & forget)
    if (attn_out) {
        float inv8[8];
#pragma unroll
        for (int h = 0; h < 8; h++) inv8[h] = 1.f / su[h];
        for (int i = lane; i < deg; i += 32) {
            float4 r0, r1;
            r0.x = s_w[w][i * NH + 0] * inv8[0];
            r0.y = s_w[w][i * NH + 1] * inv8[1];
            r0.z = s_w[w][i * NH + 2] * inv8[2];
            r0.w = s_w[w][i * NH + 3] * inv8[3];
            r1.x = s_w[w][i * NH + 4] * inv8[4];
            r1.y = s_w[w][i * NH + 5] * inv8[5];
            r1.z = s_w[w][i * NH + 6] * inv8[6];
            r1.w = s_w[w][i * NH + 7] * inv8[7];
            float4* o4 = (float4*)(attn_out + (size_t)s_se[w][i].y * NH);
            o4[0] = r0;
            o4[1] = r1;
        }
    }

    // pass4: weighted aggregation; lane covers cols 4*lane..4*lane+3
    float4 acc = make_float4(0.f, 0.f, 0.f, 0.f);
#pragma unroll 2
    for (int e = 0; e < deg; e++) {
        float wv = s_w[w][e * NH + hme];
        int s = s_se[w][e].x;
        float4 v = *(const float4*)&g_value[(size_t)s * MD + 4 * lane];
        acc.x += wv * v.x; acc.y += wv * v.y;
        acc.z += wv * v.z; acc.w += wv * v.w;
    }
    float inv = 1.f / s_red[w][hme];
    float4* o4 = (float4*)&out[(size_t)n * MD + 4 * lane];
    float4 cur = *o4;
    cur.x += acc.x * inv; cur.y += acc.y * inv;
    cur.z += acc.z * inv; cur.w += acc.w * inv;
    *o4 = cur;
}

// ---------------- K4: overflow fixup (never runs for this input) ------------
// Recomputes out + attn for any node whose degree exceeded SCAP by scanning
// the full edge list in deterministic (ascending eid) order.
__global__ void k_fixup(const int* __restrict__ ei,
                        const float* __restrict__ dist,
                        float* __restrict__ out,
                        float* __restrict__ attn_out, int E, int N) {
    int novf = g_ovf_n;
    if (novf == 0) return;
    if (novf > MAXOVF) novf = MAXOVF;
    __shared__ float s_m[NH], s_su[NH];
    __shared__ float red[256];
    int tid = threadIdx.x;
    int h8 = tid & 7;

    for (int oi = 0; oi < novf; oi++) {
        int n = g_ovf[oi];
        // skip duplicates processed earlier
        bool dup = false;
        for (int q = 0; q < oi; q++) if (g_ovf[q] == n) dup = true;
        if (dup) continue;

        float vt[8];
        for (int h = 0; h < 8; h++) vt[h] = g_vtgt[n * NH + h];

        // pass1: per-head max (threads stride edges; head = tid&7)
        float mloc = -1e30f;
        for (int e = tid >> 3; e < E; e += 32) {
            if (ei[E + e] == n) {
                float sc = g_vsrc[ei[e] * NH + h8] + vt[h8];
                sc = sc > 0.f ? sc : 0.2f * sc;
                mloc = fmaxf(mloc, sc);
            }
        }
        red[tid] = mloc;
        __syncthreads();
        if (tid < NH) {
            float v = -1e30f;
            for (int k = 0; k < 32; k++) v = fmaxf(v, red[tid + 8 * k]);
            s_m[tid] = v;
        }
        __syncthreads();
        // pass2: per-head sum
        float sloc = 0.f;
        for (int e = tid >> 3; e < E; e += 32) {
            if (ei[E + e] == n) {
                float sc = g_vsrc[ei[e] * NH + h8] + vt[h8];
                sc = sc > 0.f ? sc : 0.2f * sc;
                sloc += __expf(sc - s_m[h8]) / dist[e];
            }
        }
        red[tid] = sloc;
        __syncthreads();
        if (tid < NH) {
            float v = 0.f;
            for (int k = 0; k < 32; k++) v += red[tid + 8 * k];
            s_su[tid] = v;
        }
        __syncthreads();
        // pass3: aggregation (thread = output column, ascending e: deterministic)
        if (tid < MD) {
            int hc = tid >> 4;
            float acc = 0.f;
            for (int e = 0; e < E; e++) {
                if (ei[E + e] == n) {
                    float sc = g_vsrc[ei[e] * NH + hc] + vt[hc];
                    sc = sc > 0.f ? sc : 0.2f * sc;
                    float wv = __expf(sc - s_m[hc]) / dist[e];
                    acc += wv * g_value[(size_t)ei[e] * MD + tid];
                }
            }
            out[(size_t)n * MD + tid] += acc / s_su[hc];
        }
        // pass4: attn for this node's edges
        if (attn_out) {
            for (int e = tid >> 3; e < E; e += 32) {
                if (ei[E + e] == n) {
                    float sc = g_vsrc[ei[e] * NH + h8] + vt[h8];
                    sc = sc > 0.f ? sc : 0.2f * sc;
                    attn_out[(size_t)e * NH + h8] =
                        __expf(sc - s_m[h8]) / dist[e] / s_su[h8];
                }
            }
        }
        __syncthreads();
    }
}

// ---------------- launch -----------------------------------------------------
extern "C" void kernel_launch(void* const* d_in, const int* in_sizes, int n_in,
                              void* d_out, int out_size) {
    const float* inp   = (const float*)d_in[0];
    const int*   ei    = (const int*)d_in[1];
    const float* dist  = (const float*)d_in[2];
    // d_in[3] = deparc_edge (unused by the reference math)
    const float* Wv    = (const float*)d_in[4];
    const float* ws    = (const float*)d_in[5];
    const float* wt    = (const float*)d_in[6];
    const float* Wself = (const float*)d_in[7];
    const float* bias  = (const float*)d_in[8];

    int N = in_sizes[0] / MD;
    int E = in_sizes[2];

    float* out  = (float*)d_out;
    float* attn = nullptr;
    if ((long long)out_size >= (long long)N * MD + (long long)E * NH)
        attn = out + (size_t)N * MD;

    k_init<<<(N + 255) / 256, 256>>>(N);
    k_node<<<(N + TMN - 1) / TMN, 256>>>(inp, Wv, ws, wt, Wself, bias, out, N);
    k_build<<<(E + 255) / 256, 256>>>(ei, E);
    k_aggregate<<<(N + WPB - 1) / WPB, 32 * WPB>>>(dist, out, attn, N);
    k_fixup<<<1, 256>>>(ei, dist, out, attn, E, N);
}